// round 14
// baseline (speedup 1.0000x reference)
#include <cuda_runtime.h>
#include <cuda_bf16.h>
#include <cstdint>
#include <math.h>

// Problem constants
#define Bn   32768
#define Nn   14
#define Ed   64
#define Cd   128
#define Mrows (Bn * 14)    // 458752 = 3584 * 128
#define NT128 3584         // 128-row M-tiles
#define GRID_P 148         // persistent: 1 CTA per SM

#define WS   136           // padded bf16 row stride (272B; conflict-free ldsm)
#define IMG  34816         // one 128x128 bf16 image in smem (128*WS*2)

#define NTHREADS 320       // 8 consumer warps + 2 producer warps (reg cap 204)

// ---------------------------------------------------------------------------
// Scratch
// ---------------------------------------------------------------------------
struct __align__(16) FBuf  { float f[(size_t)Mrows * Cd]; };
struct __align__(16) HBuf  { __nv_bfloat16 h[(size_t)Mrows * Cd]; };
struct __align__(16) WBuf  { __nv_bfloat16 h[128 * WS]; };
struct __align__(16) WlpBuf{ float f[Nn * Cd]; };

__device__ FBuf   g_buf0;                      // Hpre1 / Hpre2 (fp32)
__device__ HBuf   g_a2hi, g_a2lo;              // h1 pre-split bf16 images
__device__ WlpBuf g_wlp;
__device__ float  g_c0;
__device__ WBuf   g_w1hi, g_w1lo, g_w2hi, g_w2lo;

// ---------------------------------------------------------------------------
// Helpers
// ---------------------------------------------------------------------------
__device__ __forceinline__ void cvt_hi_lo(float f, __nv_bfloat16& hi, __nv_bfloat16& lo)
{
    hi = __float2bfloat16(f);
    lo = __float2bfloat16(f - __bfloat162float(hi));
}
__device__ __forceinline__ void cvt_hi_lo2(float f0, float f1, uint32_t& hi, uint32_t& lo)
{
    __nv_bfloat16 h0, l0, h1, l1;
    cvt_hi_lo(f0, h0, l0);
    cvt_hi_lo(f1, h1, l1);
    __nv_bfloat162 hp = __halves2bfloat162(h0, h1);
    __nv_bfloat162 lp = __halves2bfloat162(l0, l1);
    hi = *reinterpret_cast<uint32_t*>(&hp);
    lo = *reinterpret_cast<uint32_t*>(&lp);
}

__device__ __forceinline__ unsigned fkey(float x)
{
    unsigned u = __float_as_uint(x);
    return u ^ ((unsigned)(((int)u) >> 31) | 0x80000000u);
}
__device__ __forceinline__ float kinv(unsigned k)
{
    unsigned u = k ^ ((k & 0x80000000u) ? 0x80000000u : 0xFFFFFFFFu);
    return __uint_as_float(u);
}

__device__ __forceinline__ uint32_t smem_u32(const void* p)
{
    uint32_t a;
    asm("{ .reg .u64 t; cvta.to.shared.u64 t, %1; cvt.u32.u64 %0, t; }"
        : "=r"(a) : "l"(p));
    return a;
}
__device__ __forceinline__ void cp16(uint32_t dst, const void* src)
{
    asm volatile("cp.async.cg.shared.global [%0], [%1], 16;"
                 :: "r"(dst), "l"(src));
}
__device__ __forceinline__ void ldsm4(uint32_t* r, uint32_t addr)
{
    asm volatile("ldmatrix.sync.aligned.m8n8.x4.shared.b16 {%0,%1,%2,%3}, [%4];"
                 : "=r"(r[0]), "=r"(r[1]), "=r"(r[2]), "=r"(r[3]) : "r"(addr));
}

// m16n8k16 bf16 MMA (base-target HMMA)
__device__ __forceinline__ void mma16816(float* d, const uint32_t* a,
                                         uint32_t b0, uint32_t b1)
{
    asm volatile(
        "mma.sync.aligned.m16n8k16.row.col.f32.bf16.bf16.f32 "
        "{%0,%1,%2,%3}, {%4,%5,%6,%7}, {%8,%9}, {%0,%1,%2,%3};"
        : "+f"(d[0]), "+f"(d[1]), "+f"(d[2]), "+f"(d[3])
        : "r"(a[0]), "r"(a[1]), "r"(a[2]), "r"(a[3]), "r"(b0), "r"(b1));
}

// ---------------------------------------------------------------------------
// Weight prep + head collapse
// ---------------------------------------------------------------------------
__global__ void prep_w_kernel(const float* __restrict__ W,
                              __nv_bfloat16* __restrict__ ohi,
                              __nv_bfloat16* __restrict__ olo)
{
    int idx = blockIdx.x * blockDim.x + threadIdx.x;
    if (idx >= 128 * 128) return;
    int n = idx >> 7, k = idx & 127;
    float w = W[k * 128 + n];
    __nv_bfloat16 hi, lo;
    cvt_hi_lo(w, hi, lo);
    ohi[n * WS + k] = hi;
    olo[n * WS + k] = lo;
}

__global__ void wlp_kernel(const float* __restrict__ Wl,
                           const float* __restrict__ Wp,
                           const float* __restrict__ bl,
                           const float* __restrict__ bp)
{
    int idx = blockIdx.x * blockDim.x + threadIdx.x;
    if (idx < Nn * Cd) {
        const float* row = Wl + (size_t)idx * 64;
        float s = 0.f;
        #pragma unroll
        for (int j = 0; j < 64; ++j) s = fmaf(row[j], Wp[j], s);
        g_wlp.f[idx] = s;
    }
    if (idx == 0) {
        float s = bp[0];
        #pragma unroll
        for (int j = 0; j < 64; ++j) s = fmaf(bl[j], Wp[j], s);
        g_c0 = s;
    }
}

// ---------------------------------------------------------------------------
// GEMM core. smem: Abuf0 hi|lo, Abuf1 hi|lo, Bhi, Blo = 6*IMG.
// Consumers: warps 0-7, warp tile 64x32, double-buffered k-step fragments.
// Producers: warps 8-9, fill the other A buffer for tile+GRID_P.
// ---------------------------------------------------------------------------
#define TG_SMEM (6 * IMG)   // 208896

struct MmaCtx {
    uint32_t aoff;
    uint32_t bA0, bA1;
    int m0, n0, g, tig;
};

__device__ __forceinline__ MmaCtx make_ctx(uint32_t sb, int tid)
{
    MmaCtx c;
    const int w = tid >> 5, lane = tid & 31;
    const int blk = lane >> 3, rw = lane & 7;
    c.m0 = (w >> 2) * 64;
    c.n0 = (w & 3) * 32;
    c.g = lane >> 2; c.tig = lane & 3;
    c.aoff = (uint32_t)(((c.m0 + rw + (blk & 1) * 8) * WS + (blk >> 1) * 8) * 2);
    const uint32_t sB = sb + 4 * IMG;
    c.bA0 = sB + ((c.n0 + rw + (blk >> 1) * 8) * WS + (blk & 1) * 8) * 2;
    c.bA1 = c.bA0 + 16 * WS * 2;
    return c;
}

// One k-step's fragments: 48 regs
struct Frags {
    uint32_t ah[4][4], al[4][4];
    uint32_t bh[2][4], bl[2][4];
};

__device__ __forceinline__ void load_frags(Frags& f, const MmaCtx& c,
                                           uint32_t abase, int k0)
{
    ldsm4(f.bh[0], c.bA0 + k0 * 2);
    ldsm4(f.bh[1], c.bA1 + k0 * 2);
    ldsm4(f.bl[0], c.bA0 + IMG + k0 * 2);
    ldsm4(f.bl[1], c.bA1 + IMG + k0 * 2);
    #pragma unroll
    for (int mb = 0; mb < 4; ++mb) {
        uint32_t ad = abase + c.aoff + (uint32_t)(mb * 16 * WS * 2 + k0 * 2);
        ldsm4(f.ah[mb], ad);
        ldsm4(f.al[mb], ad + IMG);
    }
}

__device__ __forceinline__ void mma_frags(float d[4][4][4], const Frags& f)
{
    #pragma unroll
    for (int mb = 0; mb < 4; ++mb) {
        // HH
        mma16816(d[mb][0], f.ah[mb], f.bh[0][0], f.bh[0][1]);
        mma16816(d[mb][1], f.ah[mb], f.bh[0][2], f.bh[0][3]);
        mma16816(d[mb][2], f.ah[mb], f.bh[1][0], f.bh[1][1]);
        mma16816(d[mb][3], f.ah[mb], f.bh[1][2], f.bh[1][3]);
        // HL
        mma16816(d[mb][0], f.ah[mb], f.bl[0][0], f.bl[0][1]);
        mma16816(d[mb][1], f.ah[mb], f.bl[0][2], f.bl[0][3]);
        mma16816(d[mb][2], f.ah[mb], f.bl[1][0], f.bl[1][1]);
        mma16816(d[mb][3], f.ah[mb], f.bl[1][2], f.bl[1][3]);
        // LH
        mma16816(d[mb][0], f.al[mb], f.bh[0][0], f.bh[0][1]);
        mma16816(d[mb][1], f.al[mb], f.bh[0][2], f.bh[0][3]);
        mma16816(d[mb][2], f.al[mb], f.bh[1][0], f.bh[1][1]);
        mma16816(d[mb][3], f.al[mb], f.bh[1][2], f.bh[1][3]);
    }
}

// Consumer: MMA over one A buffer (k-step fragment double-buffering), store C.
__device__ __forceinline__ void do_tile_mma(const MmaCtx& c, uint32_t abase,
                                            float* __restrict__ Cb)
{
    float d[4][4][4];
    #pragma unroll
    for (int mb = 0; mb < 4; ++mb)
        #pragma unroll
        for (int nb = 0; nb < 4; ++nb)
            #pragma unroll
            for (int j = 0; j < 4; ++j) d[mb][nb][j] = 0.f;

    Frags fr0, fr1;
    load_frags(fr0, c, abase, 0);
    #pragma unroll
    for (int ks = 0; ks < 8; ++ks) {
        if (ks < 7)
            load_frags((ks & 1) ? fr0 : fr1, c, abase, (ks + 1) * 16);
        mma_frags(d, (ks & 1) ? fr1 : fr0);
    }

    #pragma unroll
    for (int mb = 0; mb < 4; ++mb)
        #pragma unroll
        for (int nb = 0; nb < 4; ++nb) {
            int r = c.m0 + mb * 16 + c.g;
            int col = c.n0 + nb * 8 + 2 * c.tig;
            *(float2*)&Cb[r * 128 + col] =
                make_float2(d[mb][nb][0], d[mb][nb][1]);
            *(float2*)&Cb[(r + 8) * 128 + col] =
                make_float2(d[mb][nb][2], d[mb][nb][3]);
        }
}

// Producer (cvt): 64 threads cover all 4096 float4 granules (8 passes of 8).
__device__ __forceinline__ void produce_cvt(const float* __restrict__ Ab,
                                            __nv_bfloat16* dst, int p)
{
    #pragma unroll
    for (int half = 0; half < 8; ++half) {
        float4 v[8];
        #pragma unroll
        for (int j = 0; j < 8; ++j) {
            int f = p + 64 * (8 * half + j);            // 0..4095
            v[j] = *(const float4*)&Ab[(f >> 5) * 128 + ((f & 31) << 2)];
        }
        #pragma unroll
        for (int j = 0; j < 8; ++j) {
            int f = p + 64 * (8 * half + j);
            int row = f >> 5, c4 = (f & 31) << 2;
            uint32_t h0, l0, h1, l1;
            cvt_hi_lo2(v[j].x, v[j].y, h0, l0);
            cvt_hi_lo2(v[j].z, v[j].w, h1, l1);
            *(uint2*)&dst[row * WS + c4] = make_uint2(h0, h1);
            *(uint2*)&dst[IMG / 2 + row * WS + c4] = make_uint2(l0, l1);
        }
    }
}

// Producer (pre): cp.async both bf16 images (2048 granules; 64 threads x 32).
__device__ __forceinline__ void produce_pre(const __nv_bfloat16* Ahi,
                                            const __nv_bfloat16* Alo,
                                            uint32_t base, int tile, int p)
{
    const char* sh = (const char*)Ahi + (size_t)tile * 32768;
    const char* sl = (const char*)Alo + (size_t)tile * 32768;
    #pragma unroll
    for (int i = 0; i < 32; ++i) {
        int j = p + 64 * i;                  // granule 0..2047
        int row = j >> 4, gg = j & 15;
        uint32_t doff = (uint32_t)(row * WS * 2 + gg * 16);
        cp16(base + doff, sh + row * 256 + gg * 16);
        cp16(base + IMG + doff, sl + row * 256 + gg * 16);
    }
    asm volatile("cp.async.commit_group;");
}

// ---------------------------------------------------------------------------
// tgemm variant 1: A fp32, warp-specialized convert
// ---------------------------------------------------------------------------
__global__ __launch_bounds__(NTHREADS, 1) void tgemm_cvt(
    const float* __restrict__ A,
    const __nv_bfloat16* __restrict__ whi,
    const __nv_bfloat16* __restrict__ wlo,
    float* __restrict__ C)
{
    extern __shared__ __align__(16) uint8_t smem[];
    const int tid = threadIdx.x;
    const uint32_t sb = smem_u32(smem);
    __nv_bfloat16* Abuf = (__nv_bfloat16*)smem;
    const bool is_cons = (tid < 256);

    int tile = blockIdx.x;

    if (is_cons) {
        const uint4* s1 = (const uint4*)whi;
        const uint4* s2 = (const uint4*)wlo;
        #pragma unroll
        for (int i = 0; i < 9; ++i) {
            int j = tid + 256 * i;
            if (j < 2176) {
                cp16(sb + 4 * IMG + 16 * j, s1 + j);
                cp16(sb + 5 * IMG + 16 * j, s2 + j);
            }
        }
        asm volatile("cp.async.commit_group;");
        asm volatile("cp.async.wait_group 0;");
    } else {
        produce_cvt(A + (size_t)tile * 16384, Abuf, tid - 256);
    }
    __syncthreads();

    const MmaCtx ctx = make_ctx(sb, tid);
    int par = 0;

    while (true) {
        const int next = tile + GRID_P;
        const bool have = (next < NT128);

        if (is_cons) {
            do_tile_mma(ctx, sb + (uint32_t)(par * 2 * IMG),
                        C + (size_t)tile * 16384);
        } else if (have) {
            produce_cvt(A + (size_t)next * 16384,
                        Abuf + (par ^ 1) * IMG, tid - 256);
        }

        if (!have) break;
        __syncthreads();
        par ^= 1;
        tile = next;
    }
}

// ---------------------------------------------------------------------------
// tgemm variant 2: A pre-split bf16 images, producers issue cp.async
// ---------------------------------------------------------------------------
__global__ __launch_bounds__(NTHREADS, 1) void tgemm_pre(
    const __nv_bfloat16* __restrict__ Ahi,
    const __nv_bfloat16* __restrict__ Alo,
    const __nv_bfloat16* __restrict__ whi,
    const __nv_bfloat16* __restrict__ wlo,
    float* __restrict__ C)
{
    extern __shared__ __align__(16) uint8_t smem[];
    const int tid = threadIdx.x;
    const uint32_t sb = smem_u32(smem);
    const bool is_cons = (tid < 256);

    int tile = blockIdx.x;

    if (is_cons) {
        const uint4* s1 = (const uint4*)whi;
        const uint4* s2 = (const uint4*)wlo;
        #pragma unroll
        for (int i = 0; i < 9; ++i) {
            int j = tid + 256 * i;
            if (j < 2176) {
                cp16(sb + 4 * IMG + 16 * j, s1 + j);
                cp16(sb + 5 * IMG + 16 * j, s2 + j);
            }
        }
        asm volatile("cp.async.commit_group;");
        asm volatile("cp.async.wait_group 0;");
    } else {
        produce_pre(Ahi, Alo, sb, tile, tid - 256);
        asm volatile("cp.async.wait_group 0;");
    }
    __syncthreads();

    const MmaCtx ctx = make_ctx(sb, tid);
    int par = 0;

    while (true) {
        const int next = tile + GRID_P;
        const bool have = (next < NT128);

        if (is_cons) {
            do_tile_mma(ctx, sb + (uint32_t)(par * 2 * IMG),
                        C + (size_t)tile * 16384);
        } else if (have) {
            produce_pre(Ahi, Alo, sb + (uint32_t)((par ^ 1) * 2 * IMG),
                        next, tid - 256);
            asm volatile("cp.async.wait_group 0;");
        }

        if (!have) break;
        __syncthreads();
        par ^= 1;
        tile = next;
    }
}

// ---------------------------------------------------------------------------
// GAT scatter layer: warp-per-batch. CTA = 8 warps = 8 batches.
// ---------------------------------------------------------------------------
#define GW 8

template <bool LAYER2>
__global__ __launch_bounds__(256) void gat_kernel(
    const float* __restrict__ Hpre,
    const int*   __restrict__ edges,
    const float* __restrict__ a_s,
    const float* __restrict__ a_d,
    const float* __restrict__ bias,
    __nv_bfloat16* __restrict__ out_hi,
    __nv_bfloat16* __restrict__ out_lo,
    float* __restrict__ out_pred,
    float* __restrict__ out_attn)
{
    __shared__ float    s_asn[GW][16], s_adn[GW][16], s_z[GW][16];
    __shared__ unsigned s_mk[GW][16];
    __shared__ float    s_Am[GW][200];
    __shared__ __align__(16) float s_At[GW][196];

    const int tid = threadIdx.x;
    const int w = tid >> 5, lane = tid & 31;
    const int b = blockIdx.x * GW + w;

    #pragma unroll
    for (int i = 0; i < 7; ++i) {
        int j = lane + 32 * i;
        if (j < 196) { s_Am[w][j] = 0.f; if (LAYER2) s_At[w][j] = 0.f; }
    }
    if (lane < 14) { s_mk[w][lane] = 0u; s_z[w][lane] = 0.f; }

    const float* hb = Hpre + (size_t)b * (Nn * Cd);
    float4 v[Nn];
    #pragma unroll
    for (int n = 0; n < Nn; ++n)
        v[n] = *(const float4*)&hb[n * Cd + lane * 4];
    const float4 as4 = *(const float4*)&a_s[lane * 4];
    const float4 ad4 = *(const float4*)&a_d[lane * 4];
    const float4 bi4 = *(const float4*)&bias[lane * 4];

    float pa[Nn], pd[Nn];
    #pragma unroll
    for (int n = 0; n < Nn; ++n) {
        pa[n] = v[n].x * as4.x + v[n].y * as4.y + v[n].z * as4.z + v[n].w * as4.w;
        pd[n] = v[n].x * ad4.x + v[n].y * ad4.y + v[n].z * ad4.z + v[n].w * ad4.w;
    }
    #pragma unroll
    for (int o = 16; o > 0; o >>= 1) {
        #pragma unroll
        for (int n = 0; n < Nn; ++n) {
            pa[n] += __shfl_xor_sync(0xffffffffu, pa[n], o);
            pd[n] += __shfl_xor_sync(0xffffffffu, pd[n], o);
        }
    }
    if (lane == 0) {
        #pragma unroll
        for (int n = 0; n < Nn; ++n) { s_asn[w][n] = pa[n]; s_adn[w][n] = pd[n]; }
    }
    __syncwarp();

    const int* eb = edges + (size_t)b * (Ed * 2);
    int  es_[3], ed_[3];
    float lg_[3], ev_[3];
    bool act[3];
    #pragma unroll
    for (int r = 0; r < 3; ++r) {
        int e = lane + 32 * r;
        act[r] = (e < 78);
        es_[r] = 0; ed_[r] = 0; lg_[r] = 0.f;
        if (act[r]) {
            int s, dd;
            if (e < Ed) { int2 p = *(const int2*)&eb[2 * e]; s = p.x; dd = p.y; }
            else        { s = dd = e - Ed; }
            float x = s_asn[w][s] + s_adn[w][dd];
            x = (x > 0.f) ? x : 0.2f * x;
            es_[r] = s; ed_[r] = dd; lg_[r] = x;
            atomicMax(&s_mk[w][dd], fkey(x));
        }
    }
    __syncwarp();
    #pragma unroll
    for (int r = 0; r < 3; ++r) {
        if (act[r]) {
            float m = kinv(s_mk[w][ed_[r]]);
            ev_[r] = __expf(lg_[r] - m);
            atomicAdd(&s_z[w][ed_[r]], ev_[r]);
        }
    }
    __syncwarp();
    #pragma unroll
    for (int r = 0; r < 3; ++r) {
        if (act[r]) {
            float al = ev_[r] / s_z[w][ed_[r]];
            atomicAdd(&s_Am[w][ed_[r] * Nn + es_[r]], al);
            if (LAYER2) s_At[w][es_[r] * Nn + ed_[r]] = al;
        }
    }
    __syncwarp();

    if (!LAYER2) {
        #pragma unroll
        for (int n = 0; n < Nn; ++n) {
            float4 acc = bi4;
            #pragma unroll
            for (int s = 0; s < Nn; ++s) {
                float am = s_Am[w][n * Nn + s];
                acc.x = fmaf(am, v[s].x, acc.x);
                acc.y = fmaf(am, v[s].y, acc.y);
                acc.z = fmaf(am, v[s].z, acc.z);
                acc.w = fmaf(am, v[s].w, acc.w);
            }
            acc.x = fmaxf(acc.x, 0.f); acc.y = fmaxf(acc.y, 0.f);
            acc.z = fmaxf(acc.z, 0.f); acc.w = fmaxf(acc.w, 0.f);
            uint32_t h0, l0, h1, l1;
            cvt_hi_lo2(acc.x, acc.y, h0, l0);
            cvt_hi_lo2(acc.z, acc.w, h1, l1);
            size_t off = (size_t)(b * Nn + n) * 128 + lane * 4;
            *(uint2*)&out_hi[off] = make_uint2(h0, h1);
            *(uint2*)&out_lo[off] = make_uint2(l0, l1);
        }
    } else {
        float p = 0.f;
        #pragma unroll
        for (int n = 0; n < Nn; ++n) {
            float4 acc = bi4;
            #pragma unroll
            for (int s = 0; s < Nn; ++s) {
                float am = s_Am[w][n * Nn + s];
                acc.x = fmaf(am, v[s].x, acc.x);
                acc.y = fmaf(am, v[s].y, acc.y);
                acc.z = fmaf(am, v[s].z, acc.z);
                acc.w = fmaf(am, v[s].w, acc.w);
            }
            float4 wv = *(const float4*)&g_wlp.f[n * Cd + lane * 4];
            p += acc.x * wv.x + acc.y * wv.y + acc.z * wv.z + acc.w * wv.w;
        }
        #pragma unroll
        for (int o = 16; o > 0; o >>= 1)
            p += __shfl_xor_sync(0xffffffffu, p, o);
        if (lane == 0)
            out_pred[b] = 1.f / (1.f + __expf(-(p + g_c0)));
        __syncwarp();
        float* ab = out_attn + (size_t)b * (Nn * Nn);
        #pragma unroll
        for (int i = 0; i < 2; ++i) {
            int j = lane + 32 * i;
            if (j < 49)
                *(float4*)&ab[4 * j] = *(const float4*)&s_At[w][4 * j];
        }
    }
}

// ---------------------------------------------------------------------------
extern "C" void kernel_launch(void* const* d_in, const int* in_sizes, int n_in,
                              void* d_out, int out_size)
{
    const float* feature = (const float*)d_in[0];
    const int*   edges   = (const int*)  d_in[1];
    const float* W1      = (const float*)d_in[2];
    const float* a_s1    = (const float*)d_in[3];
    const float* a_d1    = (const float*)d_in[4];
    const float* b1      = (const float*)d_in[5];
    const float* W2      = (const float*)d_in[6];
    const float* a_s2    = (const float*)d_in[7];
    const float* a_d2    = (const float*)d_in[8];
    const float* b2      = (const float*)d_in[9];
    const float* Wl      = (const float*)d_in[10];
    const float* bl      = (const float*)d_in[11];
    const float* Wp      = (const float*)d_in[12];
    const float* bp      = (const float*)d_in[13];

    float* out  = (float*)d_out;
    float* pred = out;            // [B]
    float* attn = out + Bn;       // [B,N,N]

    void *p_buf0, *p_a2h, *p_a2l, *p_w1h, *p_w1l, *p_w2h, *p_w2l;
    cudaGetSymbolAddress(&p_buf0, g_buf0);
    cudaGetSymbolAddress(&p_a2h,  g_a2hi);
    cudaGetSymbolAddress(&p_a2l,  g_a2lo);
    cudaGetSymbolAddress(&p_w1h,  g_w1hi);
    cudaGetSymbolAddress(&p_w1l,  g_w1lo);
    cudaGetSymbolAddress(&p_w2h,  g_w2hi);
    cudaGetSymbolAddress(&p_w2l,  g_w2lo);
    float* buf0 = (float*)p_buf0;
    __nv_bfloat16* a2h = (__nv_bfloat16*)p_a2h;
    __nv_bfloat16* a2l = (__nv_bfloat16*)p_a2l;
    __nv_bfloat16* w1h = (__nv_bfloat16*)p_w1h;
    __nv_bfloat16* w1l = (__nv_bfloat16*)p_w1l;
    __nv_bfloat16* w2h = (__nv_bfloat16*)p_w2h;
    __nv_bfloat16* w2l = (__nv_bfloat16*)p_w2l;

    cudaFuncSetAttribute(tgemm_cvt,
                         cudaFuncAttributeMaxDynamicSharedMemorySize, TG_SMEM);
    cudaFuncSetAttribute(tgemm_pre,
                         cudaFuncAttributeMaxDynamicSharedMemorySize, TG_SMEM);

    // 0. pre-convert weights
    prep_w_kernel<<<128, 128>>>(W1, w1h, w1l);
    prep_w_kernel<<<128, 128>>>(W2, w2h, w2l);

    // 1. collapse prediction head
    wlp_kernel<<<14, 128>>>(Wl, Wp, bl, bp);

    // 2. Hpre1 = feature @ W1  (warp-specialized persistent, pipelined frags)
    tgemm_cvt<<<GRID_P, NTHREADS, TG_SMEM>>>(feature, w1h, w1l, buf0);

    // 3. GAT layer 1 -> h1 as pre-split bf16 images
    gat_kernel<false><<<Bn / GW, 256>>>(buf0, edges, a_s1, a_d1, b1,
                                        a2h, a2l, nullptr, nullptr);

    // 4. Hpre2 = h1 @ W2  (warp-specialized persistent, cp.async A)
    tgemm_pre<<<GRID_P, NTHREADS, TG_SMEM>>>(a2h, a2l, w2h, w2l, buf0);

    // 5. GAT layer 2 + attn + fused sigmoid head
    gat_kernel<true><<<Bn / GW, 256>>>(buf0, edges, a_s2, a_d2, b2,
                                       nullptr, nullptr, pred, attn);
}